// round 14
// baseline (speedup 1.0000x reference)
#include <cuda_runtime.h>
#include <cuda_fp16.h>
#include <cstdint>

#define NN 50000
#define NM 4
#define DD 128
#define NE 800000
#define ALPHA 0.05f
#define EPS 1e-5f

#define TOTROWS (NN * NM)            // 200000
#define BST 136                      // B^T row stride in fp16 (68 u32 words)
#define CST 132                      // C staging row stride (floats)

#define P_ROWS 128
#define P_CTAS ((TOTROWS + P_ROWS - 1) / P_ROWS)   // 1563
#define AROWS_PAD (P_CTAS * P_ROWS)                // 200064
#define SMEM_P 67584                 // max(Bh 34816, C 67584)

// ---------------------------------------------------------------------------
// Device globals
// ---------------------------------------------------------------------------
__device__ int   g_count[NN];        // zeroed by previous call's fill_csr (BSS-zero first call)
__device__ int   g_off[NN + 1];
__device__ int   g_rank[NE];         // edge's within-dst rank (from hist atomic return)
__device__ uint2 g_edge[NE];         // packed (src, w-bits) sorted by dst
__device__ int   g_bsum[64];
__device__ __half g_xh[(size_t)NN * NM * DD];              // fp16 x, 51.2 MB
__device__ __align__(16) __half g_Bt[DD * BST];            // W^T (fp16)
__device__ __align__(16) uint32_t g_A[(size_t)AROWS_PAD * 64];   // fp16 agg, 51.2 MB

// ---------------------------------------------------------------------------
// Prologue: pack B (fp16) + histogram dst (saving ranks) + convert x->fp16
// ---------------------------------------------------------------------------
__global__ void prep_conv_kernel(const float* __restrict__ W,
                                 const float2* __restrict__ xf2,
                                 const int* __restrict__ dst) {
    int i = blockIdx.x * blockDim.x + threadIdx.x;
    if (i < DD * BST) {
        int n = i / BST, k = i % BST;
        float v = (k < DD) ? W[k * DD + n] : 0.f;
        g_Bt[i] = __float2half_rn(v);
    }
    if (i < NE) g_rank[i] = atomicAdd(&g_count[dst[i]], 1);
    if (i < NN * NM * DD / 2)
        reinterpret_cast<__half2*>(g_xh)[i] = __float22half2_rn(xf2[i]);
}

// ---------------------------------------------------------------------------
// Coalesced two-phase scan (proven shape)
// ---------------------------------------------------------------------------
__global__ void __launch_bounds__(1024) scan1_kernel() {
    __shared__ int s[1024];
    int i = blockIdx.x * 1024 + threadIdx.x;
    int v = (i < NN) ? g_count[i] : 0;
    s[threadIdx.x] = v;
    __syncthreads();
#pragma unroll
    for (int o = 1; o < 1024; o <<= 1) {
        int t = (threadIdx.x >= o) ? s[threadIdx.x - o] : 0;
        __syncthreads();
        s[threadIdx.x] += t;
        __syncthreads();
    }
    if (i < NN) g_off[i] = s[threadIdx.x] - v;
    if (threadIdx.x == 1023) g_bsum[blockIdx.x] = s[1023];
}

__global__ void __launch_bounds__(1024) scan23_kernel() {
    __shared__ int sb[64];
    const int tid = threadIdx.x;
    if (tid < 64) sb[tid] = (tid < 49) ? g_bsum[tid] : 0;
    __syncthreads();
#pragma unroll
    for (int o = 1; o < 64; o <<= 1) {
        int t = (tid < 64 && tid >= o) ? sb[tid - o] : 0;
        __syncthreads();
        if (tid < 64) sb[tid] += t;
        __syncthreads();
    }
    const int base = (blockIdx.x > 0) ? sb[blockIdx.x - 1] : 0;
    int i = blockIdx.x * 1024 + tid;
    if (i < NN) g_off[i] += base;
    if (blockIdx.x == 0 && tid == 0) g_off[NN] = NE;
}

// ---------------------------------------------------------------------------
// fill_csr (atomic-free): pos = off[dst] + rank. 4 edges/thread (MLP on the
// off/rank loads) + resets g_count for the next graph replay.
// ---------------------------------------------------------------------------
__global__ void fill_csr_kernel(const int* __restrict__ src,
                                const int* __restrict__ dst,
                                const float* __restrict__ w) {
    int gid = blockIdx.x * blockDim.x + threadIdx.x;
    int e0 = gid * 4;
    int t_[4], r_[4];
#pragma unroll
    for (int j = 0; j < 4; j++) {
        int e = e0 + j;
        if (e < NE) {
            t_[j] = __ldg(&dst[e]);
            r_[j] = g_rank[e];
        }
    }
#pragma unroll
    for (int j = 0; j < 4; j++) {
        int e = e0 + j;
        if (e < NE) {
            int pos = g_off[t_[j]] + r_[j];
            g_edge[pos] = make_uint2((uint32_t)__ldg(&src[e]), __float_as_uint(__ldg(&w[e])));
        }
    }
    if (gid < NN) g_count[gid] = 0;   // reset for next call
}

// ---------------------------------------------------------------------------
// Gather: 4 nodes per 256-thr CTA; 64 threads per node, uint4 (16 B) slices.
// Unroll x4 (64 B in flight per thread), u32 addressing.
// ---------------------------------------------------------------------------
__global__ void __launch_bounds__(256) gather_kernel() {
    const int sub  = threadIdx.x >> 6;           // 0..3: node within CTA
    const int tt   = threadIdx.x & 63;           // 16B chunk of the 1024B row
    const int node = blockIdx.x * 4 + sub;

    const int b = g_off[node], e = g_off[node + 1];
    float a0 = 0.f, a1 = 0.f, a2 = 0.f, a3 = 0.f;
    float a4 = 0.f, a5 = 0.f, a6 = 0.f, a7 = 0.f;
    const uint4* xh4 = reinterpret_cast<const uint4*>(g_xh);

    int q = b;
    for (; q + 3 < e; q += 4) {
        uint2 ed[4];
        uint4 xv[4];
#pragma unroll
        for (int j = 0; j < 4; j++) ed[j] = __ldg(&g_edge[q + j]);
#pragma unroll
        for (int j = 0; j < 4; j++) xv[j] = __ldg(&xh4[ed[j].x * 64u + (uint32_t)tt]);
#pragma unroll
        for (int j = 0; j < 4; j++) {
            float wj = __uint_as_float(ed[j].y);
            float2 p0 = __half22float2(*reinterpret_cast<__half2*>(&xv[j].x));
            float2 p1 = __half22float2(*reinterpret_cast<__half2*>(&xv[j].y));
            float2 p2 = __half22float2(*reinterpret_cast<__half2*>(&xv[j].z));
            float2 p3 = __half22float2(*reinterpret_cast<__half2*>(&xv[j].w));
            a0 = fmaf(wj, p0.x, a0); a1 = fmaf(wj, p0.y, a1);
            a2 = fmaf(wj, p1.x, a2); a3 = fmaf(wj, p1.y, a3);
            a4 = fmaf(wj, p2.x, a4); a5 = fmaf(wj, p2.y, a5);
            a6 = fmaf(wj, p3.x, a6); a7 = fmaf(wj, p3.y, a7);
        }
    }
    for (; q < e; q++) {
        uint2 e0 = __ldg(&g_edge[q]);
        uint4 v0 = __ldg(&xh4[e0.x * 64u + (uint32_t)tt]);
        float w0 = __uint_as_float(e0.y);
        float2 p0 = __half22float2(*reinterpret_cast<__half2*>(&v0.x));
        float2 p1 = __half22float2(*reinterpret_cast<__half2*>(&v0.y));
        float2 p2 = __half22float2(*reinterpret_cast<__half2*>(&v0.z));
        float2 p3 = __half22float2(*reinterpret_cast<__half2*>(&v0.w));
        a0 = fmaf(w0, p0.x, a0); a1 = fmaf(w0, p0.y, a1);
        a2 = fmaf(w0, p1.x, a2); a3 = fmaf(w0, p1.y, a3);
        a4 = fmaf(w0, p2.x, a4); a5 = fmaf(w0, p2.y, a5);
        a6 = fmaf(w0, p3.x, a6); a7 = fmaf(w0, p3.y, a7);
    }

    __half2 h0 = __float22half2_rn(make_float2(a0, a1));
    __half2 h1 = __float22half2_rn(make_float2(a2, a3));
    __half2 h2 = __float22half2_rn(make_float2(a4, a5));
    __half2 h3 = __float22half2_rn(make_float2(a6, a7));
    uint4 pkt;
    pkt.x = *reinterpret_cast<uint32_t*>(&h0);
    pkt.y = *reinterpret_cast<uint32_t*>(&h1);
    pkt.z = *reinterpret_cast<uint32_t*>(&h2);
    pkt.w = *reinterpret_cast<uint32_t*>(&h3);

    const size_t row = (size_t)node * NM + (tt >> 4);
    *reinterpret_cast<uint4*>(&g_A[row * 64 + (tt & 15) * 4]) = pkt;
}

// ---------------------------------------------------------------------------
// mma.sync fp16 (sm_80 baseline)
// ---------------------------------------------------------------------------
__device__ __forceinline__ void mma_f16(float c[4],
                                        uint32_t a0, uint32_t a1, uint32_t a2, uint32_t a3,
                                        uint32_t b0, uint32_t b1) {
    asm volatile(
        "mma.sync.aligned.m16n8k16.row.col.f32.f16.f16.f32 "
        "{%0,%1,%2,%3}, {%4,%5,%6,%7}, {%8,%9}, {%0,%1,%2,%3};"
        : "+f"(c[0]), "+f"(c[1]), "+f"(c[2]), "+f"(c[3])
        : "r"(a0), "r"(a1), "r"(a2), "r"(a3), "r"(b0), "r"(b1));
}

// ---------------------------------------------------------------------------
// GEMM + residual + LN. 1563 CTAs x 256 thr, 128 rows/CTA. Single-B fp16.
// ---------------------------------------------------------------------------
__global__ void __launch_bounds__(256, 2) gemmln_kernel(
    const float4* __restrict__ gamma4,
    const float4* __restrict__ beta4,
    float4* __restrict__ out4)
{
    extern __shared__ char sm[];
    uint32_t* Bh = reinterpret_cast<uint32_t*>(sm);            // [128][68] words
    float*    Cf = reinterpret_cast<float*>(sm);               // overlay after mma

    const int tid  = threadIdx.x;
    const int wid  = tid >> 5;
    const int lane = tid & 31;
    const int g    = lane >> 2;
    const int t    = lane & 3;

    {
        const uint4* sh = reinterpret_cast<const uint4*>(g_Bt);
        uint4* dh = reinterpret_cast<uint4*>(Bh);
        const int n16 = DD * BST * 2 / 16;   // 2176
        for (int i = tid; i < n16; i += 256) dh[i] = sh[i];
    }
    __syncthreads();

    const size_t rowbase = (size_t)blockIdx.x * P_ROWS;
    const int r0 = wid * 16;

    float c[16][4];
#pragma unroll
    for (int nt = 0; nt < 16; nt++)
#pragma unroll
        for (int j = 0; j < 4; j++) c[nt][j] = 0.f;

#pragma unroll
    for (int kt = 0; kt < 8; kt++) {
        const size_t ra = (rowbase + r0 + g) * 64 + kt * 8 + t;
        const size_t rb = (rowbase + r0 + g + 8) * 64 + kt * 8 + t;
        uint32_t a0 = __ldg(&g_A[ra]);
        uint32_t a1 = __ldg(&g_A[rb]);
        uint32_t a2 = __ldg(&g_A[ra + 4]);
        uint32_t a3 = __ldg(&g_A[rb + 4]);
#pragma unroll
        for (int nt = 0; nt < 16; nt++) {
            const int bw = (nt * 8 + g) * 68 + kt * 8 + t;
            mma_f16(c[nt], a0, a1, a2, a3, Bh[bw], Bh[bw + 4]);
        }
    }
    __syncthreads();   // B reads done -> overlay C

    {
        const int rg = r0 + g;
#pragma unroll
        for (int nt = 0; nt < 16; nt++) {
            const int col = nt * 8 + 2 * t;
            *reinterpret_cast<float2*>(&Cf[rg * CST + col])       = make_float2(c[nt][0], c[nt][1]);
            *reinterpret_cast<float2*>(&Cf[(rg + 8) * CST + col]) = make_float2(c[nt][2], c[nt][3]);
        }
    }
    __syncthreads();

    const uint2* xh2 = reinterpret_cast<const uint2*>(g_xh);
#pragma unroll
    for (int i = 0; i < 16; i++) {
        const int row = wid * 16 + i;
        const size_t grow = rowbase + row;
        if (grow >= TOTROWS) break;
        float4 cv = *reinterpret_cast<float4*>(&Cf[row * CST + lane * 4]);
        uint2 xv2 = __ldg(&xh2[grow * 32 + lane]);
        float2 x01 = __half22float2(*reinterpret_cast<__half2*>(&xv2.x));
        float2 x23 = __half22float2(*reinterpret_cast<__half2*>(&xv2.y));

        float y0 = fmaf(ALPHA, cv.x, x01.x);
        float y1 = fmaf(ALPHA, cv.y, x01.y);
        float y2 = fmaf(ALPHA, cv.z, x23.x);
        float y3 = fmaf(ALPHA, cv.w, x23.y);

        float s  = y0 + y1 + y2 + y3;
        float ss = y0 * y0 + y1 * y1 + y2 * y2 + y3 * y3;
#pragma unroll
        for (int o = 16; o > 0; o >>= 1) {
            s  += __shfl_xor_sync(0xFFFFFFFFu, s, o);
            ss += __shfl_xor_sync(0xFFFFFFFFu, ss, o);
        }
        const float inv_d = 1.f / (float)DD;
        float mu  = s * inv_d;
        float var = ss * inv_d - mu * mu;
        float inv = rsqrtf(var + EPS);

        float4 gm = __ldg(&gamma4[lane]);
        float4 bt = __ldg(&beta4[lane]);
        float4 o4;
        o4.x = fmaf((y0 - mu) * inv, gm.x, bt.x);
        o4.y = fmaf((y1 - mu) * inv, gm.y, bt.y);
        o4.z = fmaf((y2 - mu) * inv, gm.z, bt.z);
        o4.w = fmaf((y3 - mu) * inv, gm.w, bt.w);
        out4[grow * 32 + lane] = o4;
    }
}

// ---------------------------------------------------------------------------
extern "C" void kernel_launch(void* const* d_in, const int* in_sizes, int n_in,
                              void* d_out, int out_size) {
    const float* multimodal = (const float*)d_in[0];
    const int*   edge_src   = (const int*)d_in[1];
    const int*   edge_dst   = (const int*)d_in[2];
    const float* edge_w     = (const float*)d_in[3];
    const float* W          = (const float*)d_in[4];
    const float* gamma      = (const float*)d_in[5];
    const float* beta       = (const float*)d_in[6];
    float* out = (float*)d_out;

    cudaFuncSetAttribute(gemmln_kernel, cudaFuncAttributeMaxDynamicSharedMemorySize,
                         SMEM_P);

    const int SCAN_BLOCKS = (NN + 1023) / 1024;  // 49
    const int PREP_BLOCKS = (NN * NM * DD / 2 + 255) / 256;

    prep_conv_kernel<<<PREP_BLOCKS, 256>>>(W, (const float2*)multimodal, edge_dst);
    scan1_kernel<<<SCAN_BLOCKS, 1024>>>();
    scan23_kernel<<<SCAN_BLOCKS, 1024>>>();
    fill_csr_kernel<<<(NE / 4 + 255) / 256, 256>>>(edge_src, edge_dst, edge_w);

    gather_kernel<<<NN / 4, 256>>>();
    gemmln_kernel<<<P_CTAS, 256, SMEM_P>>>(
        (const float4*)gamma, (const float4*)beta, (float4*)out);
}

// round 15
// speedup vs baseline: 1.0080x; 1.0080x over previous
#include <cuda_runtime.h>
#include <cuda_fp16.h>
#include <cstdint>

#define NN 50000
#define NM 4
#define DD 128
#define NE 800000
#define ALPHA 0.05f
#define EPS 1e-5f

#define TOTROWS (NN * NM)            // 200000
#define BST 136                      // B^T row stride in fp16 (68 u32 words)

#define P_ROWS 128
#define P_CTAS ((TOTROWS + P_ROWS - 1) / P_ROWS)   // 1563
#define AROWS_PAD (P_CTAS * P_ROWS)                // 200064
#define SMEM_P 34816                 // B only (no C staging)

// ---------------------------------------------------------------------------
// Device globals
// ---------------------------------------------------------------------------
__device__ int   g_count[NN];        // zeroed by previous call's fill_csr (BSS-zero first call)
__device__ int   g_off[NN + 1];
__device__ int   g_rank[NE];         // edge's within-dst rank (from hist atomic return)
__device__ uint2 g_edge[NE];         // packed (src, w-bits) sorted by dst
__device__ int   g_bsum[64];
__device__ __half g_xh[(size_t)NN * NM * DD];              // fp16 x, 51.2 MB
__device__ __align__(16) __half g_Bt[DD * BST];            // W^T (fp16)
__device__ __align__(16) uint32_t g_A[(size_t)AROWS_PAD * 64];   // fp16 agg, 51.2 MB

// ---------------------------------------------------------------------------
// Prologue: pack B (fp16) + histogram dst (saving ranks) + convert x->fp16
// ---------------------------------------------------------------------------
__global__ void prep_conv_kernel(const float* __restrict__ W,
                                 const float2* __restrict__ xf2,
                                 const int* __restrict__ dst) {
    int i = blockIdx.x * blockDim.x + threadIdx.x;
    if (i < DD * BST) {
        int n = i / BST, k = i % BST;
        float v = (k < DD) ? W[k * DD + n] : 0.f;
        g_Bt[i] = __float2half_rn(v);
    }
    if (i < NE) g_rank[i] = atomicAdd(&g_count[dst[i]], 1);
    if (i < NN * NM * DD / 2)
        reinterpret_cast<__half2*>(g_xh)[i] = __float22half2_rn(xf2[i]);
}

// ---------------------------------------------------------------------------
// Coalesced two-phase scan (proven shape)
// ---------------------------------------------------------------------------
__global__ void __launch_bounds__(1024) scan1_kernel() {
    __shared__ int s[1024];
    int i = blockIdx.x * 1024 + threadIdx.x;
    int v = (i < NN) ? g_count[i] : 0;
    s[threadIdx.x] = v;
    __syncthreads();
#pragma unroll
    for (int o = 1; o < 1024; o <<= 1) {
        int t = (threadIdx.x >= o) ? s[threadIdx.x - o] : 0;
        __syncthreads();
        s[threadIdx.x] += t;
        __syncthreads();
    }
    if (i < NN) g_off[i] = s[threadIdx.x] - v;
    if (threadIdx.x == 1023) g_bsum[blockIdx.x] = s[1023];
}

__global__ void __launch_bounds__(1024) scan23_kernel() {
    __shared__ int sb[64];
    const int tid = threadIdx.x;
    if (tid < 64) sb[tid] = (tid < 49) ? g_bsum[tid] : 0;
    __syncthreads();
#pragma unroll
    for (int o = 1; o < 64; o <<= 1) {
        int t = (tid < 64 && tid >= o) ? sb[tid - o] : 0;
        __syncthreads();
        if (tid < 64) sb[tid] += t;
        __syncthreads();
    }
    const int base = (blockIdx.x > 0) ? sb[blockIdx.x - 1] : 0;
    int i = blockIdx.x * 1024 + tid;
    if (i < NN) g_off[i] += base;
    if (blockIdx.x == 0 && tid == 0) g_off[NN] = NE;
}

// ---------------------------------------------------------------------------
// fill_csr (atomic-free, proven): pos = off[dst] + rank. 4 edges/thread.
// ---------------------------------------------------------------------------
__global__ void fill_csr_kernel(const int* __restrict__ src,
                                const int* __restrict__ dst,
                                const float* __restrict__ w) {
    int gid = blockIdx.x * blockDim.x + threadIdx.x;
    int e0 = gid * 4;
    int t_[4], r_[4];
#pragma unroll
    for (int j = 0; j < 4; j++) {
        int e = e0 + j;
        if (e < NE) {
            t_[j] = __ldg(&dst[e]);
            r_[j] = g_rank[e];
        }
    }
#pragma unroll
    for (int j = 0; j < 4; j++) {
        int e = e0 + j;
        if (e < NE) {
            int pos = g_off[t_[j]] + r_[j];
            g_edge[pos] = make_uint2((uint32_t)__ldg(&src[e]), __float_as_uint(__ldg(&w[e])));
        }
    }
    if (gid < NN) g_count[gid] = 0;   // reset for next call
}

// ---------------------------------------------------------------------------
// Gather (revert to R13's measured-good shape): 2 nodes per 128-thr CTA;
// 64 threads per node, uint4 slices, unroll x4, u32 addressing.
// ---------------------------------------------------------------------------
__global__ void __launch_bounds__(128) gather_kernel() {
    const int sub  = threadIdx.x >> 6;           // 0..1: node within CTA
    const int tt   = threadIdx.x & 63;           // 16B chunk of the 1024B row
    const int node = blockIdx.x * 2 + sub;

    const int b = g_off[node], e = g_off[node + 1];
    float a0 = 0.f, a1 = 0.f, a2 = 0.f, a3 = 0.f;
    float a4 = 0.f, a5 = 0.f, a6 = 0.f, a7 = 0.f;
    const uint4* xh4 = reinterpret_cast<const uint4*>(g_xh);

    int q = b;
    for (; q + 3 < e; q += 4) {
        uint2 ed[4];
        uint4 xv[4];
#pragma unroll
        for (int j = 0; j < 4; j++) ed[j] = __ldg(&g_edge[q + j]);
#pragma unroll
        for (int j = 0; j < 4; j++) xv[j] = __ldg(&xh4[ed[j].x * 64u + (uint32_t)tt]);
#pragma unroll
        for (int j = 0; j < 4; j++) {
            float wj = __uint_as_float(ed[j].y);
            float2 p0 = __half22float2(*reinterpret_cast<__half2*>(&xv[j].x));
            float2 p1 = __half22float2(*reinterpret_cast<__half2*>(&xv[j].y));
            float2 p2 = __half22float2(*reinterpret_cast<__half2*>(&xv[j].z));
            float2 p3 = __half22float2(*reinterpret_cast<__half2*>(&xv[j].w));
            a0 = fmaf(wj, p0.x, a0); a1 = fmaf(wj, p0.y, a1);
            a2 = fmaf(wj, p1.x, a2); a3 = fmaf(wj, p1.y, a3);
            a4 = fmaf(wj, p2.x, a4); a5 = fmaf(wj, p2.y, a5);
            a6 = fmaf(wj, p3.x, a6); a7 = fmaf(wj, p3.y, a7);
        }
    }
    for (; q < e; q++) {
        uint2 e0 = __ldg(&g_edge[q]);
        uint4 v0 = __ldg(&xh4[e0.x * 64u + (uint32_t)tt]);
        float w0 = __uint_as_float(e0.y);
        float2 p0 = __half22float2(*reinterpret_cast<__half2*>(&v0.x));
        float2 p1 = __half22float2(*reinterpret_cast<__half2*>(&v0.y));
        float2 p2 = __half22float2(*reinterpret_cast<__half2*>(&v0.z));
        float2 p3 = __half22float2(*reinterpret_cast<__half2*>(&v0.w));
        a0 = fmaf(w0, p0.x, a0); a1 = fmaf(w0, p0.y, a1);
        a2 = fmaf(w0, p1.x, a2); a3 = fmaf(w0, p1.y, a3);
        a4 = fmaf(w0, p2.x, a4); a5 = fmaf(w0, p2.y, a5);
        a6 = fmaf(w0, p3.x, a6); a7 = fmaf(w0, p3.y, a7);
    }

    __half2 h0 = __float22half2_rn(make_float2(a0, a1));
    __half2 h1 = __float22half2_rn(make_float2(a2, a3));
    __half2 h2 = __float22half2_rn(make_float2(a4, a5));
    __half2 h3 = __float22half2_rn(make_float2(a6, a7));
    uint4 pkt;
    pkt.x = *reinterpret_cast<uint32_t*>(&h0);
    pkt.y = *reinterpret_cast<uint32_t*>(&h1);
    pkt.z = *reinterpret_cast<uint32_t*>(&h2);
    pkt.w = *reinterpret_cast<uint32_t*>(&h3);

    const size_t row = (size_t)node * NM + (tt >> 4);
    *reinterpret_cast<uint4*>(&g_A[row * 64 + (tt & 15) * 4]) = pkt;
}

// ---------------------------------------------------------------------------
// mma.sync fp16 (sm_80 baseline)
// ---------------------------------------------------------------------------
__device__ __forceinline__ void mma_f16(float c[4],
                                        uint32_t a0, uint32_t a1, uint32_t a2, uint32_t a3,
                                        uint32_t b0, uint32_t b1) {
    asm volatile(
        "mma.sync.aligned.m16n8k16.row.col.f32.f16.f16.f32 "
        "{%0,%1,%2,%3}, {%4,%5,%6,%7}, {%8,%9}, {%0,%1,%2,%3};"
        : "+f"(c[0]), "+f"(c[1]), "+f"(c[2]), "+f"(c[3])
        : "r"(a0), "r"(a1), "r"(a2), "r"(a3), "r"(b0), "r"(b1));
}

// ---------------------------------------------------------------------------
// GEMM + residual + LN, in-register epilogue (no C staging).
// Thread (wid,g,t) holds rows r0+g / r0+g+8, cols {nt*8+2t, nt*8+2t+1}.
// Quad (same g, t=0..3) holds each full 128-col row -> LN via 2 shfl_xor.
// ---------------------------------------------------------------------------
__global__ void __launch_bounds__(256, 2) gemmln_kernel(
    const float2* __restrict__ gamma2,
    const float2* __restrict__ beta2,
    float2* __restrict__ out2)
{
    extern __shared__ char sm[];
    uint32_t* Bh = reinterpret_cast<uint32_t*>(sm);            // [128][68] words

    const int tid  = threadIdx.x;
    const int wid  = tid >> 5;
    const int lane = tid & 31;
    const int g    = lane >> 2;
    const int t    = lane & 3;

    {
        const uint4* sh = reinterpret_cast<const uint4*>(g_Bt);
        uint4* dh = reinterpret_cast<uint4*>(Bh);
        const int n16 = DD * BST * 2 / 16;   // 2176
        for (int i = tid; i < n16; i += 256) dh[i] = sh[i];
    }
    __syncthreads();

    const size_t rowbase = (size_t)blockIdx.x * P_ROWS;
    const int r0 = wid * 16;

    float c[16][4];
#pragma unroll
    for (int nt = 0; nt < 16; nt++)
#pragma unroll
        for (int j = 0; j < 4; j++) c[nt][j] = 0.f;

#pragma unroll
    for (int kt = 0; kt < 8; kt++) {
        const size_t ra = (rowbase + r0 + g) * 64 + kt * 8 + t;
        const size_t rb = (rowbase + r0 + g + 8) * 64 + kt * 8 + t;
        uint32_t a0 = __ldg(&g_A[ra]);
        uint32_t a1 = __ldg(&g_A[rb]);
        uint32_t a2 = __ldg(&g_A[ra + 4]);
        uint32_t a3 = __ldg(&g_A[rb + 4]);
#pragma unroll
        for (int nt = 0; nt < 16; nt++) {
            const int bw = (nt * 8 + g) * 68 + kt * 8 + t;
            mma_f16(c[nt], a0, a1, a2, a3, Bh[bw], Bh[bw + 4]);
        }
    }

    // ---- in-register residual + LN ----
    const size_t growA = rowbase + r0 + g;
    const size_t growB = growA + 8;
    const bool okA = (growA < TOTROWS), okB = (growB < TOTROWS);
    const __half2* xh2 = reinterpret_cast<const __half2*>(g_xh);

    float sA = 0.f, ssA = 0.f, sB = 0.f, ssB = 0.f;
#pragma unroll
    for (int nt = 0; nt < 16; nt++) {
        const int cidx = nt * 4 + t;   // half2 index of cols {nt*8+2t, +1}
        if (okA) {
            float2 xA = __half22float2(xh2[growA * 64 + cidx]);
            float y0 = fmaf(ALPHA, c[nt][0], xA.x);
            float y1 = fmaf(ALPHA, c[nt][1], xA.y);
            c[nt][0] = y0; c[nt][1] = y1;
            sA += y0 + y1; ssA += y0 * y0 + y1 * y1;
        }
        if (okB) {
            float2 xB = __half22float2(xh2[growB * 64 + cidx]);
            float y2 = fmaf(ALPHA, c[nt][2], xB.x);
            float y3 = fmaf(ALPHA, c[nt][3], xB.y);
            c[nt][2] = y2; c[nt][3] = y3;
            sB += y2 + y3; ssB += y2 * y2 + y3 * y3;
        }
    }
    // quad reduction (t dimension): masks 1 and 2
#pragma unroll
    for (int m = 1; m <= 2; m <<= 1) {
        sA  += __shfl_xor_sync(0xFFFFFFFFu, sA, m);
        ssA += __shfl_xor_sync(0xFFFFFFFFu, ssA, m);
        sB  += __shfl_xor_sync(0xFFFFFFFFu, sB, m);
        ssB += __shfl_xor_sync(0xFFFFFFFFu, ssB, m);
    }
    const float inv_d = 1.f / (float)DD;
    float muA = sA * inv_d, varA = ssA * inv_d - muA * muA;
    float muB = sB * inv_d, varB = ssB * inv_d - muB * muB;
    float invA = rsqrtf(varA + EPS);
    float invB = rsqrtf(varB + EPS);

#pragma unroll
    for (int nt = 0; nt < 16; nt++) {
        const int cidx = nt * 4 + t;
        float2 gm = __ldg(&gamma2[cidx]);
        float2 bt = __ldg(&beta2[cidx]);
        if (okA) {
            float2 o;
            o.x = fmaf((c[nt][0] - muA) * invA, gm.x, bt.x);
            o.y = fmaf((c[nt][1] - muA) * invA, gm.y, bt.y);
            out2[growA * 64 + cidx] = o;
        }
        if (okB) {
            float2 o;
            o.x = fmaf((c[nt][2] - muB) * invB, gm.x, bt.x);
            o.y = fmaf((c[nt][3] - muB) * invB, gm.y, bt.y);
            out2[growB * 64 + cidx] = o;
        }
    }
}

// ---------------------------------------------------------------------------
extern "C" void kernel_launch(void* const* d_in, const int* in_sizes, int n_in,
                              void* d_out, int out_size) {
    const float* multimodal = (const float*)d_in[0];
    const int*   edge_src   = (const int*)d_in[1];
    const int*   edge_dst   = (const int*)d_in[2];
    const float* edge_w     = (const float*)d_in[3];
    const float* W          = (const float*)d_in[4];
    const float* gamma      = (const float*)d_in[5];
    const float* beta       = (const float*)d_in[6];
    float* out = (float*)d_out;

    cudaFuncSetAttribute(gemmln_kernel, cudaFuncAttributeMaxDynamicSharedMemorySize,
                         SMEM_P);

    const int SCAN_BLOCKS = (NN + 1023) / 1024;  // 49
    const int PREP_BLOCKS = (NN * NM * DD / 2 + 255) / 256;

    prep_conv_kernel<<<PREP_BLOCKS, 256>>>(W, (const float2*)multimodal, edge_dst);
    scan1_kernel<<<SCAN_BLOCKS, 1024>>>();
    scan23_kernel<<<SCAN_BLOCKS, 1024>>>();
    fill_csr_kernel<<<(NE / 4 + 255) / 256, 256>>>(edge_src, edge_dst, edge_w);

    gather_kernel<<<NN / 2, 128>>>();
    gemmln_kernel<<<P_CTAS, 256, SMEM_P>>>(
        (const float2*)gamma, (const float2*)beta, (float2*)out);
}

// round 16
// speedup vs baseline: 1.0188x; 1.0107x over previous
#include <cuda_runtime.h>
#include <cuda_fp16.h>
#include <cstdint>

#define NN 50000
#define NM 4
#define DD 128
#define NE 800000
#define ALPHA 0.05f
#define EPS 1e-5f

#define TOTROWS (NN * NM)            // 200000
#define BST 136                      // B^T row stride in fp16 (68 u32 words)
#define CST 132                      // C staging row stride (floats)

#define P_ROWS 128
#define P_CTAS ((TOTROWS + P_ROWS - 1) / P_ROWS)   // 1563
#define AROWS_PAD (P_CTAS * P_ROWS)                // 200064
#define SMEM_P 67584                 // max(Bh 34816, C 67584)

// ---------------------------------------------------------------------------
// Device globals
// ---------------------------------------------------------------------------
__device__ int   g_count[NN];        // zeroed by previous call's fill_csr (BSS-zero first call)
__device__ int   g_off[NN + 1];
__device__ int   g_rank[NE];         // edge's within-dst rank (from hist atomic return)
__device__ uint2 g_edge[NE];         // packed (src, w-bits) sorted by dst
__device__ int   g_bsum[64];
__device__ __half g_xh[(size_t)NN * NM * DD];              // fp16 x, 51.2 MB
__device__ __align__(16) __half g_Bt[DD * BST];            // W^T (fp16)
__device__ __align__(16) uint32_t g_A[(size_t)AROWS_PAD * 64];   // fp16 agg, 51.2 MB

// ---------------------------------------------------------------------------
// Prologue: pack B (fp16) + histogram dst (saving ranks) + convert x->fp16
// ---------------------------------------------------------------------------
__global__ void prep_conv_kernel(const float* __restrict__ W,
                                 const float2* __restrict__ xf2,
                                 const int* __restrict__ dst) {
    int i = blockIdx.x * blockDim.x + threadIdx.x;
    if (i < DD * BST) {
        int n = i / BST, k = i % BST;
        float v = (k < DD) ? W[k * DD + n] : 0.f;
        g_Bt[i] = __float2half_rn(v);
    }
    if (i < NE) g_rank[i] = atomicAdd(&g_count[dst[i]], 1);
    if (i < NN * NM * DD / 2)
        reinterpret_cast<__half2*>(g_xh)[i] = __float22half2_rn(xf2[i]);
}

// ---------------------------------------------------------------------------
// Coalesced two-phase scan (proven shape)
// ---------------------------------------------------------------------------
__global__ void __launch_bounds__(1024) scan1_kernel() {
    __shared__ int s[1024];
    int i = blockIdx.x * 1024 + threadIdx.x;
    int v = (i < NN) ? g_count[i] : 0;
    s[threadIdx.x] = v;
    __syncthreads();
#pragma unroll
    for (int o = 1; o < 1024; o <<= 1) {
        int t = (threadIdx.x >= o) ? s[threadIdx.x - o] : 0;
        __syncthreads();
        s[threadIdx.x] += t;
        __syncthreads();
    }
    if (i < NN) g_off[i] = s[threadIdx.x] - v;
    if (threadIdx.x == 1023) g_bsum[blockIdx.x] = s[1023];
}

__global__ void __launch_bounds__(1024) scan23_kernel() {
    __shared__ int sb[64];
    const int tid = threadIdx.x;
    if (tid < 64) sb[tid] = (tid < 49) ? g_bsum[tid] : 0;
    __syncthreads();
#pragma unroll
    for (int o = 1; o < 64; o <<= 1) {
        int t = (tid < 64 && tid >= o) ? sb[tid - o] : 0;
        __syncthreads();
        if (tid < 64) sb[tid] += t;
        __syncthreads();
    }
    const int base = (blockIdx.x > 0) ? sb[blockIdx.x - 1] : 0;
    int i = blockIdx.x * 1024 + tid;
    if (i < NN) g_off[i] += base;
    if (blockIdx.x == 0 && tid == 0) g_off[NN] = NE;
}

// ---------------------------------------------------------------------------
// fill_csr (atomic-free, measured 12.0us): pos = off[dst] + rank.
// 4 edges/thread + resets g_count for the next graph replay.
// ---------------------------------------------------------------------------
__global__ void fill_csr_kernel(const int* __restrict__ src,
                                const int* __restrict__ dst,
                                const float* __restrict__ w) {
    int gid = blockIdx.x * blockDim.x + threadIdx.x;
    int e0 = gid * 4;
    int t_[4], r_[4];
#pragma unroll
    for (int j = 0; j < 4; j++) {
        int e = e0 + j;
        if (e < NE) {
            t_[j] = __ldg(&dst[e]);
            r_[j] = g_rank[e];
        }
    }
#pragma unroll
    for (int j = 0; j < 4; j++) {
        int e = e0 + j;
        if (e < NE) {
            int pos = g_off[t_[j]] + r_[j];
            g_edge[pos] = make_uint2((uint32_t)__ldg(&src[e]), __float_as_uint(__ldg(&w[e])));
        }
    }
    if (gid < NN) g_count[gid] = 0;   // reset for next call
}

// ---------------------------------------------------------------------------
// Gather (R13 measured-good shape): 2 nodes per 128-thr CTA; 64 threads per
// node, uint4 slices, unroll x4, u32 addressing.
// ---------------------------------------------------------------------------
__global__ void __launch_bounds__(128) gather_kernel() {
    const int sub  = threadIdx.x >> 6;           // 0..1: node within CTA
    const int tt   = threadIdx.x & 63;           // 16B chunk of the 1024B row
    const int node = blockIdx.x * 2 + sub;

    const int b = g_off[node], e = g_off[node + 1];
    float a0 = 0.f, a1 = 0.f, a2 = 0.f, a3 = 0.f;
    float a4 = 0.f, a5 = 0.f, a6 = 0.f, a7 = 0.f;
    const uint4* xh4 = reinterpret_cast<const uint4*>(g_xh);

    int q = b;
    for (; q + 3 < e; q += 4) {
        uint2 ed[4];
        uint4 xv[4];
#pragma unroll
        for (int j = 0; j < 4; j++) ed[j] = __ldg(&g_edge[q + j]);
#pragma unroll
        for (int j = 0; j < 4; j++) xv[j] = __ldg(&xh4[ed[j].x * 64u + (uint32_t)tt]);
#pragma unroll
        for (int j = 0; j < 4; j++) {
            float wj = __uint_as_float(ed[j].y);
            float2 p0 = __half22float2(*reinterpret_cast<__half2*>(&xv[j].x));
            float2 p1 = __half22float2(*reinterpret_cast<__half2*>(&xv[j].y));
            float2 p2 = __half22float2(*reinterpret_cast<__half2*>(&xv[j].z));
            float2 p3 = __half22float2(*reinterpret_cast<__half2*>(&xv[j].w));
            a0 = fmaf(wj, p0.x, a0); a1 = fmaf(wj, p0.y, a1);
            a2 = fmaf(wj, p1.x, a2); a3 = fmaf(wj, p1.y, a3);
            a4 = fmaf(wj, p2.x, a4); a5 = fmaf(wj, p2.y, a5);
            a6 = fmaf(wj, p3.x, a6); a7 = fmaf(wj, p3.y, a7);
        }
    }
    for (; q < e; q++) {
        uint2 e0 = __ldg(&g_edge[q]);
        uint4 v0 = __ldg(&xh4[e0.x * 64u + (uint32_t)tt]);
        float w0 = __uint_as_float(e0.y);
        float2 p0 = __half22float2(*reinterpret_cast<__half2*>(&v0.x));
        float2 p1 = __half22float2(*reinterpret_cast<__half2*>(&v0.y));
        float2 p2 = __half22float2(*reinterpret_cast<__half2*>(&v0.z));
        float2 p3 = __half22float2(*reinterpret_cast<__half2*>(&v0.w));
        a0 = fmaf(w0, p0.x, a0); a1 = fmaf(w0, p0.y, a1);
        a2 = fmaf(w0, p1.x, a2); a3 = fmaf(w0, p1.y, a3);
        a4 = fmaf(w0, p2.x, a4); a5 = fmaf(w0, p2.y, a5);
        a6 = fmaf(w0, p3.x, a6); a7 = fmaf(w0, p3.y, a7);
    }

    __half2 h0 = __float22half2_rn(make_float2(a0, a1));
    __half2 h1 = __float22half2_rn(make_float2(a2, a3));
    __half2 h2 = __float22half2_rn(make_float2(a4, a5));
    __half2 h3 = __float22half2_rn(make_float2(a6, a7));
    uint4 pkt;
    pkt.x = *reinterpret_cast<uint32_t*>(&h0);
    pkt.y = *reinterpret_cast<uint32_t*>(&h1);
    pkt.z = *reinterpret_cast<uint32_t*>(&h2);
    pkt.w = *reinterpret_cast<uint32_t*>(&h3);

    const size_t row = (size_t)node * NM + (tt >> 4);
    *reinterpret_cast<uint4*>(&g_A[row * 64 + (tt & 15) * 4]) = pkt;
}

// ---------------------------------------------------------------------------
// mma.sync fp16 (sm_80 baseline)
// ---------------------------------------------------------------------------
__device__ __forceinline__ void mma_f16(float c[4],
                                        uint32_t a0, uint32_t a1, uint32_t a2, uint32_t a3,
                                        uint32_t b0, uint32_t b1) {
    asm volatile(
        "mma.sync.aligned.m16n8k16.row.col.f32.f16.f16.f32 "
        "{%0,%1,%2,%3}, {%4,%5,%6,%7}, {%8,%9}, {%0,%1,%2,%3};"
        : "+f"(c[0]), "+f"(c[1]), "+f"(c[2]), "+f"(c[3])
        : "r"(a0), "r"(a1), "r"(a2), "r"(a3), "r"(b0), "r"(b1));
}

// ---------------------------------------------------------------------------
// GEMM + residual + LN (R13's measured configuration: single-B fp16,
// C staged through smem, coalesced LN epilogue).
// ---------------------------------------------------------------------------
__global__ void __launch_bounds__(256, 2) gemmln_kernel(
    const float4* __restrict__ gamma4,
    const float4* __restrict__ beta4,
    float4* __restrict__ out4)
{
    extern __shared__ char sm[];
    uint32_t* Bh = reinterpret_cast<uint32_t*>(sm);            // [128][68] words
    float*    Cf = reinterpret_cast<float*>(sm);               // overlay after mma

    const int tid  = threadIdx.x;
    const int wid  = tid >> 5;
    const int lane = tid & 31;
    const int g    = lane >> 2;
    const int t    = lane & 3;

    {
        const uint4* sh = reinterpret_cast<const uint4*>(g_Bt);
        uint4* dh = reinterpret_cast<uint4*>(Bh);
        const int n16 = DD * BST * 2 / 16;   // 2176
        for (int i = tid; i < n16; i += 256) dh[i] = sh[i];
    }
    __syncthreads();

    const size_t rowbase = (size_t)blockIdx.x * P_ROWS;
    const int r0 = wid * 16;

    float c[16][4];
#pragma unroll
    for (int nt = 0; nt < 16; nt++)
#pragma unroll
        for (int j = 0; j < 4; j++) c[nt][j] = 0.f;

#pragma unroll
    for (int kt = 0; kt < 8; kt++) {
        const size_t ra = (rowbase + r0 + g) * 64 + kt * 8 + t;
        const size_t rb = (rowbase + r0 + g + 8) * 64 + kt * 8 + t;
        uint32_t a0 = __ldg(&g_A[ra]);
        uint32_t a1 = __ldg(&g_A[rb]);
        uint32_t a2 = __ldg(&g_A[ra + 4]);
        uint32_t a3 = __ldg(&g_A[rb + 4]);
#pragma unroll
        for (int nt = 0; nt < 16; nt++) {
            const int bw = (nt * 8 + g) * 68 + kt * 8 + t;
            mma_f16(c[nt], a0, a1, a2, a3, Bh[bw], Bh[bw + 4]);
        }
    }
    __syncthreads();   // B reads done -> overlay C

    {
        const int rg = r0 + g;
#pragma unroll
        for (int nt = 0; nt < 16; nt++) {
            const int col = nt * 8 + 2 * t;
            *reinterpret_cast<float2*>(&Cf[rg * CST + col])       = make_float2(c[nt][0], c[nt][1]);
            *reinterpret_cast<float2*>(&Cf[(rg + 8) * CST + col]) = make_float2(c[nt][2], c[nt][3]);
        }
    }
    __syncthreads();

    const uint2* xh2 = reinterpret_cast<const uint2*>(g_xh);
#pragma unroll
    for (int i = 0; i < 16; i++) {
        const int row = wid * 16 + i;
        const size_t grow = rowbase + row;
        if (grow >= TOTROWS) break;
        float4 cv = *reinterpret_cast<float4*>(&Cf[row * CST + lane * 4]);
        uint2 xv2 = __ldg(&xh2[grow * 32 + lane]);
        float2 x01 = __half22float2(*reinterpret_cast<__half2*>(&xv2.x));
        float2 x23 = __half22float2(*reinterpret_cast<__half2*>(&xv2.y));

        float y0 = fmaf(ALPHA, cv.x, x01.x);
        float y1 = fmaf(ALPHA, cv.y, x01.y);
        float y2 = fmaf(ALPHA, cv.z, x23.x);
        float y3 = fmaf(ALPHA, cv.w, x23.y);

        float s  = y0 + y1 + y2 + y3;
        float ss = y0 * y0 + y1 * y1 + y2 * y2 + y3 * y3;
#pragma unroll
        for (int o = 16; o > 0; o >>= 1) {
            s  += __shfl_xor_sync(0xFFFFFFFFu, s, o);
            ss += __shfl_xor_sync(0xFFFFFFFFu, ss, o);
        }
        const float inv_d = 1.f / (float)DD;
        float mu  = s * inv_d;
        float var = ss * inv_d - mu * mu;
        float inv = rsqrtf(var + EPS);

        float4 gm = __ldg(&gamma4[lane]);
        float4 bt = __ldg(&beta4[lane]);
        float4 o4;
        o4.x = fmaf((y0 - mu) * inv, gm.x, bt.x);
        o4.y = fmaf((y1 - mu) * inv, gm.y, bt.y);
        o4.z = fmaf((y2 - mu) * inv, gm.z, bt.z);
        o4.w = fmaf((y3 - mu) * inv, gm.w, bt.w);
        out4[grow * 32 + lane] = o4;
    }
}

// ---------------------------------------------------------------------------
extern "C" void kernel_launch(void* const* d_in, const int* in_sizes, int n_in,
                              void* d_out, int out_size) {
    const float* multimodal = (const float*)d_in[0];
    const int*   edge_src   = (const int*)d_in[1];
    const int*   edge_dst   = (const int*)d_in[2];
    const float* edge_w     = (const float*)d_in[3];
    const float* W          = (const float*)d_in[4];
    const float* gamma      = (const float*)d_in[5];
    const float* beta       = (const float*)d_in[6];
    float* out = (float*)d_out;

    cudaFuncSetAttribute(gemmln_kernel, cudaFuncAttributeMaxDynamicSharedMemorySize,
                         SMEM_P);

    const int SCAN_BLOCKS = (NN + 1023) / 1024;  // 49
    const int PREP_BLOCKS = (NN * NM * DD / 2 + 255) / 256;

    prep_conv_kernel<<<PREP_BLOCKS, 256>>>(W, (const float2*)multimodal, edge_dst);
    scan1_kernel<<<SCAN_BLOCKS, 1024>>>();
    scan23_kernel<<<SCAN_BLOCKS, 1024>>>();
    fill_csr_kernel<<<(NE / 4 + 255) / 256, 256>>>(edge_src, edge_dst, edge_w);

    gather_kernel<<<NN / 2, 128>>>();
    gemmln_kernel<<<P_CTAS, 256, SMEM_P>>>(
        (const float4*)gamma, (const float4*)beta, (float4*)out);
}